// round 5
// baseline (speedup 1.0000x reference)
#include <cuda_runtime.h>
#include <cuda_bf16.h>

// MeanAggregator: out[r,:] = mean over UNIQUE neighbors c of row r of embed[c,:]
// row_idx sorted ascending. D = 300 floats = 75 float4.
// Design: 2 warps per row, split along the NEIGHBOR dim (even/odd interleave),
// full-width coalesced gather per warp (3 LDG.128 per neighbor), combine via smem.

#define AGG_D4   75
#define AGG_MAXL 192           // per-row staged unique cap (L ~ Poisson(32), max ~70)
#define AGG_MAXB 65536
#define ROWS_PB  4             // rows per block -> 8 warps / 256 threads

__device__ int g_row_start[AGG_MAXB + 1];

// CSR row pointers by diff-scatter over the sorted row_idx (O(E), contiguous loads).
__global__ void build_row_starts(const int* __restrict__ row_idx, int E, int B) {
    int i = blockIdx.x * blockDim.x + threadIdx.x;
    if (i > E) return;
    if (i == 0) {
        int cur = row_idx[0];
        for (int v = 0; v <= cur; ++v) g_row_start[v] = 0;
    } else if (i == E) {
        int prev = row_idx[E - 1];
        for (int v = prev + 1; v <= B; ++v) g_row_start[v] = E;
    } else {
        int prev = row_idx[i - 1];
        int cur  = row_idx[i];
        for (int v = prev + 1; v <= cur; ++v) g_row_start[v] = i;
    }
}

__global__ __launch_bounds__(ROWS_PB * 64) void mean_agg_kernel(
    const int*    __restrict__ col_idx,
    const float4* __restrict__ embed4,   // [U, 75]
    float4*       __restrict__ out4,     // [B, 75]
    int B)
{
    const int w    = threadIdx.x >> 5;        // 0..7
    const int lane = threadIdx.x & 31;
    const int rloc = w >> 1;                  // row slot in block
    const int half = w & 1;                   // neighbor-dim half
    const int r    = blockIdx.x * ROWS_PB + rloc;
    const bool active = (r < B);

    // su shared per ROW: both warps of the pair write IDENTICAL values (benign
    // write-write race); each warp only reads entries it has itself written.
    __shared__ int    s_uniq[ROWS_PB][AGG_MAXL];
    __shared__ float4 s_part[ROWS_PB][AGG_D4];   // partial sums from half==1

    int* su = s_uniq[rloc];

    int start = 0, L = 0;
    if (active) {
        start = g_row_start[r];
        L     = g_row_start[r + 1] - start;
    }

    float4 a0 = make_float4(0.f, 0.f, 0.f, 0.f);
    float4 a1 = a0, a2 = a0;
    const unsigned lt   = (1u << lane) - 1u;
    const bool     has3 = (lane < AGG_D4 - 64);   // lanes 0..10 own slot lane+64
    int Lu = 0;

    if (active && L <= AGG_MAXL) {
        // ---- warp-synchronous order-preserving dedup (run identically by both warps) ----
        for (int base = 0; base < L; base += 32) {
            int  j   = base + lane;
            bool inb = (j < L);
            int  c   = inb ? col_idx[start + j] : -(lane + 1);
            unsigned peers = __match_any_sync(0xffffffffu, c);
            bool valid = inb && ((peers & lt) == 0);
            if (valid) {
                for (int i = 0; i < Lu; ++i)
                    if (su[i] == c) { valid = false; break; }
            }
            unsigned m = __ballot_sync(0xffffffffu, valid);
            if (valid) su[Lu + __popc(m & lt)] = c;
            Lu += __popc(m);
            __syncwarp();
        }

        // ---- gather own half: neighbors half, half+2, ... full-width 3-LDG each ----
        const float4* __restrict__ e = embed4 + lane;
        int j = half;
        for (; j + 6 < Lu; j += 8) {              // 4 neighbors per batch
            const float4* p0 = e + (size_t)su[j]     * AGG_D4;
            const float4* p1 = e + (size_t)su[j + 2] * AGG_D4;
            const float4* p2 = e + (size_t)su[j + 4] * AGG_D4;
            const float4* p3 = e + (size_t)su[j + 6] * AGG_D4;
            float4 x0 = p0[0],  x1 = p1[0],  x2 = p2[0],  x3 = p3[0];
            float4 y0 = p0[32], y1 = p1[32], y2 = p2[32], y3 = p3[32];
            if (has3) {
                float4 z0 = p0[64], z1 = p1[64], z2 = p2[64], z3 = p3[64];
                a2.x += z0.x + z1.x + z2.x + z3.x;
                a2.y += z0.y + z1.y + z2.y + z3.y;
                a2.z += z0.z + z1.z + z2.z + z3.z;
                a2.w += z0.w + z1.w + z2.w + z3.w;
            }
            a0.x += x0.x + x1.x + x2.x + x3.x;
            a0.y += x0.y + x1.y + x2.y + x3.y;
            a0.z += x0.z + x1.z + x2.z + x3.z;
            a0.w += x0.w + x1.w + x2.w + x3.w;
            a1.x += y0.x + y1.x + y2.x + y3.x;
            a1.y += y0.y + y1.y + y2.y + y3.y;
            a1.z += y0.z + y1.z + y2.z + y3.z;
            a1.w += y0.w + y1.w + y2.w + y3.w;
        }
        for (; j < Lu; j += 2) {
            const float4* p = e + (size_t)su[j] * AGG_D4;
            float4 x = p[0], y = p[32];
            if (has3) {
                float4 z = p[64];
                a2.x += z.x; a2.y += z.y; a2.z += z.z; a2.w += z.w;
            }
            a0.x += x.x; a0.y += x.y; a0.z += x.z; a0.w += x.w;
            a1.x += y.x; a1.y += y.y; a1.z += y.z; a1.w += y.w;
        }
    } else if (active) {
        // Unreachable-for-this-data fallback: O(L^2) global dedup; same even/odd split.
        int seen = 0;
        for (int j = 0; j < L; ++j) {
            int c = col_idx[start + j];
            bool valid = true;
            for (int i = 0; i < j; ++i)
                if (col_idx[start + i] == c) { valid = false; break; }
            if (!valid) continue;
            int my = seen++;                  // unique ordinal
            if ((my & 1) != half) continue;
            const float4* p = embed4 + (size_t)c * AGG_D4 + lane;
            float4 x = p[0], y = p[32];
            if (has3) {
                float4 z = p[64];
                a2.x += z.x; a2.y += z.y; a2.z += z.z; a2.w += z.w;
            }
            a0.x += x.x; a0.y += x.y; a0.z += x.z; a0.w += x.w;
            a1.x += y.x; a1.y += y.y; a1.z += y.z; a1.w += y.w;
        }
        Lu = seen;
    }

    // ---- combine halves (half 1 -> smem, half 0 adds and writes) ----
    if (active && half == 1) {
        s_part[rloc][lane]      = a0;
        s_part[rloc][lane + 32] = a1;
        if (has3) s_part[rloc][lane + 64] = a2;
    }
    __syncthreads();
    if (active && half == 0) {
        const float inv = 1.0f / fmaxf((float)Lu, 1e-8f);
        float4* o = out4 + (size_t)r * AGG_D4 + lane;
        float4 b0 = s_part[rloc][lane];
        float4 b1 = s_part[rloc][lane + 32];
        float4 t;
        t.x = (a0.x + b0.x) * inv; t.y = (a0.y + b0.y) * inv;
        t.z = (a0.z + b0.z) * inv; t.w = (a0.w + b0.w) * inv;
        o[0] = t;
        t.x = (a1.x + b1.x) * inv; t.y = (a1.y + b1.y) * inv;
        t.z = (a1.z + b1.z) * inv; t.w = (a1.w + b1.w) * inv;
        o[32] = t;
        if (has3) {
            float4 b2 = s_part[rloc][lane + 64];
            t.x = (a2.x + b2.x) * inv; t.y = (a2.y + b2.y) * inv;
            t.z = (a2.z + b2.z) * inv; t.w = (a2.w + b2.w) * inv;
            o[64] = t;
        }
    }
}

extern "C" void kernel_launch(void* const* d_in, const int* in_sizes, int n_in,
                              void* d_out, int out_size) {
    const int*   row_idx = (const int*)  d_in[0];
    const int*   col_idx = (const int*)  d_in[1];
    const float* embed   = (const float*)d_in[2];
    float*       out     = (float*)      d_out;

    const int E = in_sizes[0];
    const int B = out_size / 300;

    build_row_starts<<<(E + 1 + 255) / 256, 256>>>(row_idx, E, B);
    mean_agg_kernel<<<(B + ROWS_PB - 1) / ROWS_PB, ROWS_PB * 64>>>(
        col_idx, (const float4*)embed, (float4*)out, B);
}

// round 6
// speedup vs baseline: 1.1000x; 1.1000x over previous
#include <cuda_runtime.h>
#include <cuda_bf16.h>

// MeanAggregator: out[r,:] = mean over UNIQUE neighbors c of row r of embed[c,:]
// row_idx sorted ascending. D = 300 floats = 75 float4. Warp-per-row.
// Set semantics via GATHER-ALL + SUBTRACT-DUPLICATES (dups are ~1% of rows):
// sum over all L entries, then subtract embed rows of duplicate occurrences,
// divide by (L - ndup). Exact, deterministic, removes the dedup phase from
// the critical path.

#define AGG_D4   75
#define AGG_MAXL 96            // fast-path cap: 3 chunks (L ~ Poisson(32), max ~70)
#define AGG_MAXB 65536
#define ROWS_PB  4             // warps (rows) per 128-thread block

__device__ int g_row_start[AGG_MAXB + 1];

// CSR row pointers by diff-scatter over the sorted row_idx (O(E), contiguous loads).
__global__ void build_row_starts(const int* __restrict__ row_idx, int E, int B) {
    int i = blockIdx.x * blockDim.x + threadIdx.x;
    if (i > E) return;
    if (i == 0) {
        int cur = row_idx[0];
        for (int v = 0; v <= cur; ++v) g_row_start[v] = 0;
    } else if (i == E) {
        int prev = row_idx[E - 1];
        for (int v = prev + 1; v <= B; ++v) g_row_start[v] = E;
    } else {
        int prev = row_idx[i - 1];
        int cur  = row_idx[i];
        for (int v = prev + 1; v <= cur; ++v) g_row_start[v] = i;
    }
}

__global__ __launch_bounds__(ROWS_PB * 32) void mean_agg_kernel(
    const int*    __restrict__ col_idx,
    const float4* __restrict__ embed4,   // [U, 75]
    float4*       __restrict__ out4,     // [B, 75]
    int B)
{
    const int w    = threadIdx.x >> 5;
    const int lane = threadIdx.x & 31;
    const int r    = blockIdx.x * ROWS_PB + w;
    if (r >= B) return;                       // warp-uniform

    const int start = g_row_start[r];
    const int L     = g_row_start[r + 1] - start;

    __shared__ int s_col[ROWS_PB][AGG_MAXL];
    int* sc = s_col[w];

    float4 a0 = make_float4(0.f, 0.f, 0.f, 0.f);
    float4 a1 = a0, a2 = a0;
    const unsigned lt   = (1u << lane) - 1u;
    const bool     has3 = (lane < AGG_D4 - 64);
    const float4* __restrict__ e = embed4 + lane;
    int Lu = 0;

    if (L <= AGG_MAXL) {
        // ---- 3 independent coalesced chunk loads of col indices ----
        const int j1 = 32 + lane, j2 = 64 + lane;
        int c0 = (lane < L) ? col_idx[start + lane] : -(lane + 1);
        int c1 = (j1   < L) ? col_idx[start + j1]   : -(lane + 1);
        int c2 = (j2   < L) ? col_idx[start + j2]   : -(lane + 1);
        sc[lane] = c0;
        if (j1 < L) sc[j1] = c1;
        if (j2 < L) sc[j2] = c2;
        __syncwarp();

        // ---- duplicate detection (cheap; rarely finds anything) ----
        unsigned p0 = __match_any_sync(0xffffffffu, c0);
        bool d0 = (lane < L) && ((p0 & lt) != 0);
        bool d1 = false, d2 = false;
        if (L > 32) {
            unsigned p1 = __match_any_sync(0xffffffffu, c1);
            d1 = (j1 < L) && ((p1 & lt) != 0);
            if (!d1 && j1 < L) {
                for (int i = 0; i < 32; ++i)
                    if (sc[i] == c1) { d1 = true; break; }
            }
            if (L > 64) {
                unsigned p2 = __match_any_sync(0xffffffffu, c2);
                d2 = (j2 < L) && ((p2 & lt) != 0);
                if (!d2 && j2 < L) {
                    for (int i = 0; i < 64; ++i)
                        if (sc[i] == c2) { d2 = true; break; }
                }
            }
        }
        const unsigned m0 = __ballot_sync(0xffffffffu, d0);
        const unsigned m1 = __ballot_sync(0xffffffffu, d1);
        const unsigned m2 = __ballot_sync(0xffffffffu, d2);
        Lu = L - (__popc(m0) + __popc(m1) + __popc(m2));

        // ---- main gather over ALL L entries: unroll-4, 12 LDG.128 in flight ----
        int j = 0;
        for (; j + 4 <= L; j += 4) {
            const float4* p0 = e + (size_t)sc[j]     * AGG_D4;
            const float4* p1 = e + (size_t)sc[j + 1] * AGG_D4;
            const float4* p2 = e + (size_t)sc[j + 2] * AGG_D4;
            const float4* p3 = e + (size_t)sc[j + 3] * AGG_D4;
            float4 x0 = p0[0],  x1 = p1[0],  x2 = p2[0],  x3 = p3[0];
            float4 y0 = p0[32], y1 = p1[32], y2 = p2[32], y3 = p3[32];
            if (has3) {
                float4 z0 = p0[64], z1 = p1[64], z2 = p2[64], z3 = p3[64];
                a2.x += z0.x + z1.x + z2.x + z3.x;
                a2.y += z0.y + z1.y + z2.y + z3.y;
                a2.z += z0.z + z1.z + z2.z + z3.z;
                a2.w += z0.w + z1.w + z2.w + z3.w;
            }
            a0.x += x0.x + x1.x + x2.x + x3.x;
            a0.y += x0.y + x1.y + x2.y + x3.y;
            a0.z += x0.z + x1.z + x2.z + x3.z;
            a0.w += x0.w + x1.w + x2.w + x3.w;
            a1.x += y0.x + y1.x + y2.x + y3.x;
            a1.y += y0.y + y1.y + y2.y + y3.y;
            a1.z += y0.z + y1.z + y2.z + y3.z;
            a1.w += y0.w + y1.w + y2.w + y3.w;
        }
        for (; j < L; ++j) {
            const float4* p = e + (size_t)sc[j] * AGG_D4;
            float4 x = p[0], y = p[32];
            if (has3) {
                float4 z = p[64];
                a2.x += z.x; a2.y += z.y; a2.z += z.z; a2.w += z.w;
            }
            a0.x += x.x; a0.y += x.y; a0.z += x.z; a0.w += x.w;
            a1.x += y.x; a1.y += y.y; a1.z += y.z; a1.w += y.w;
        }

        // ---- subtract duplicate occurrences (almost always all-zero masks) ----
        if (m0 | m1 | m2) {
            unsigned masks[3] = { m0, m1, m2 };
            #pragma unroll
            for (int k = 0; k < 3; ++k) {
                unsigned m = masks[k];
                while (m) {
                    int b = __ffs(m) - 1; m &= m - 1;
                    const float4* p = e + (size_t)sc[k * 32 + b] * AGG_D4;
                    float4 x = p[0], y = p[32];
                    if (has3) {
                        float4 z = p[64];
                        a2.x -= z.x; a2.y -= z.y; a2.z -= z.z; a2.w -= z.w;
                    }
                    a0.x -= x.x; a0.y -= x.y; a0.z -= x.z; a0.w -= x.w;
                    a1.x -= y.x; a1.y -= y.y; a1.z -= y.z; a1.w -= y.w;
                }
            }
        }
    } else {
        // Unreachable-for-this-data fallback: O(L^2) global dedup, direct accumulate.
        for (int j = 0; j < L; ++j) {
            int c = col_idx[start + j];
            bool valid = true;
            for (int i = 0; i < j; ++i)
                if (col_idx[start + i] == c) { valid = false; break; }
            if (!valid) continue;
            ++Lu;
            const float4* p = e + (size_t)c * AGG_D4;
            float4 x = p[0], y = p[32];
            if (has3) {
                float4 z = p[64];
                a2.x += z.x; a2.y += z.y; a2.z += z.z; a2.w += z.w;
            }
            a0.x += x.x; a0.y += x.y; a0.z += x.z; a0.w += x.w;
            a1.x += y.x; a1.y += y.y; a1.z += y.z; a1.w += y.w;
        }
    }

    const float inv = 1.0f / fmaxf((float)Lu, 1e-8f);
    float4* o = out4 + (size_t)r * AGG_D4 + lane;
    float4 t;
    t.x = a0.x * inv; t.y = a0.y * inv; t.z = a0.z * inv; t.w = a0.w * inv;
    o[0] = t;
    t.x = a1.x * inv; t.y = a1.y * inv; t.z = a1.z * inv; t.w = a1.w * inv;
    o[32] = t;
    if (has3) {
        t.x = a2.x * inv; t.y = a2.y * inv; t.z = a2.z * inv; t.w = a2.w * inv;
        o[64] = t;
    }
}

extern "C" void kernel_launch(void* const* d_in, const int* in_sizes, int n_in,
                              void* d_out, int out_size) {
    const int*   row_idx = (const int*)  d_in[0];
    const int*   col_idx = (const int*)  d_in[1];
    const float* embed   = (const float*)d_in[2];
    float*       out     = (float*)      d_out;

    const int E = in_sizes[0];
    const int B = out_size / 300;

    build_row_starts<<<(E + 1 + 255) / 256, 256>>>(row_idx, E, B);
    mean_agg_kernel<<<(B + ROWS_PB - 1) / ROWS_PB, ROWS_PB * 32>>>(
        col_idx, (const float4*)embed, (float4*)out, B);
}